// round 6
// baseline (speedup 1.0000x reference)
#include <cuda_runtime.h>
#include <math.h>

// Problem constants
#define CC    128
#define HW    4096
#define NPIX  8192
#define NCLS  4
#define KSEL  50
#define KPAD  56                       // 8 k-groups x 7
#define NBIN  1024
#define MAXCAND 1024
#define SCALE 20.6099291555566197f     // log2(e)/0.07
#define NBLK  128
#define NTHR  512

#define RS 132                         // padded row stride (floats) for X/P tiles
#define CS (KPAD * CC + 4)             // class stride (floats): 7172

// smem layout (float offsets)
#define OFF_X    0
#define OFF_P    8448
#define OFF_G    16896
#define OFF_RED  45584                 // 3*8*64
#define OFF_EX   47120                 // 16*64
#define OFF_INV  48144
#define OFF_INVP 48208
#define OFF_NOM  48272
#define OFF_CLS  48336
#define OFF_PERM 48400
#define OFF_SLOT 48464
#define OFF_CNT  48528
#define SMEM_FLOATS 48544
#define SMEM_BYTES  (SMEM_FLOATS * 4)  // 194176

typedef unsigned long long u64;

__device__ __forceinline__ void fma2(u64& acc, u64 a, u64 b) {
    asm("fma.rn.f32x2 %0, %1, %2, %0;" : "+l"(acc) : "l"(a), "l"(b));
}
__device__ __forceinline__ float2 upk(u64 v) {
    float2 r; asm("mov.b64 {%0,%1}, %2;" : "=f"(r.x), "=f"(r.y) : "l"(v)); return r;
}

// ---------------- device scratch ----------------
__device__ float g_Gs[NCLS][KPAD][CC];  // selected negatives, normalized AND pre-scaled by SCALE
__device__ int   g_segneg[NPIX];
__device__ float g_negprob[NPIX];
__device__ float g_acc;
__device__ unsigned int g_tick;
__device__ unsigned int g_bar_cnt;
__device__ volatile unsigned int g_bar_gen;

// self-resetting grid barrier; all NBLK blocks are guaranteed co-resident
// (grid=128 <= 148 SMs, 1 CTA/SM by smem).
__device__ __forceinline__ void grid_barrier() {
    __syncthreads();
    if (threadIdx.x == 0) {
        unsigned int gen = g_bar_gen;
        __threadfence();
        if (atomicAdd(&g_bar_cnt, 1u) == NBLK - 1) {
            g_bar_cnt = 0;
            __threadfence();
            g_bar_gen = gen + 1;
        } else {
            while (g_bar_gen == gen) __nanosleep(64);
        }
        __threadfence();
    }
    __syncthreads();
}

__global__ __launch_bounds__(NTHR, 1) void k_all(const float* __restrict__ inp,
                                                 const float* __restrict__ pos,
                                                 const float* __restrict__ neg,
                                                 const float* __restrict__ il,
                                                 const float* __restrict__ nl,
                                                 float* __restrict__ out) {
    extern __shared__ float sm[];
    float* sX    = sm + OFF_X;
    float* sP    = sm + OFF_P;
    float* sG    = sm + OFF_G;
    float* sRed  = sm + OFF_RED;
    float* sEx   = sm + OFF_EX;
    float* sInv  = sm + OFF_INV;
    float* sInvP = sm + OFF_INVP;
    float* sNom  = sm + OFF_NOM;
    int*   sCls  = (int*)(sm + OFF_CLS);
    int*   sPerm = (int*)(sm + OFF_PERM);
    int*   sSlot = (int*)(sm + OFF_SLOT);
    int*   sCnt  = (int*)(sm + OFF_CNT);

    int tid = threadIdx.x;
    int n   = tid & 63;
    int cg  = tid >> 6;                  // 0..7 channel group
    int blk = blockIdx.x;
    int px0 = blk * 64;
    int b   = px0 >> 12, rem = px0 & 4095;

    if (blk == 0 && tid == 0) g_acc = 0.0f;
    if (tid < 8) sCnt[tid] = 0;

    // ======== Phase 1: x/p load + norms; seg for own pixels ========
    float xv[16], pv[16];
    {
        const float* bx = inp + (size_t)b * CC * HW + rem + n;
        const float* bp = pos + (size_t)b * CC * HW + rem + n;
        float sx2 = 0.f, sp2 = 0.f, sxp = 0.f;
        #pragma unroll
        for (int j = 0; j < 16; j++) {
            int c = cg * 16 + j;
            xv[j] = bx[(size_t)c * HW];
            pv[j] = bp[(size_t)c * HW];
            sx2 += xv[j] * xv[j];
            sp2 += pv[j] * pv[j];
            sxp += xv[j] * pv[j];
        }
        sRed[(0 * 8 + cg) * 64 + n] = sx2;
        sRed[(1 * 8 + cg) * 64 + n] = sp2;
        sRed[(2 * 8 + cg) * 64 + n] = sxp;
    }
    if (tid < 64) {
        // input class (for GEMM routing)
        const float* pi = il + (size_t)b * NCLS * HW + rem + tid;
        float l0 = pi[0], l1 = pi[HW], l2 = pi[2 * HW], l3 = pi[3 * HW];
        int amax = 0; float m = l0;
        if (l1 > m) { m = l1; amax = 1; }
        if (l2 > m) { m = l2; amax = 2; }
        if (l3 > m) { m = l3; amax = 3; }
        sCls[tid] = amax;
    } else if (tid < 128) {
        // negative class + max-softmax prob -> global (consumed by phase 2)
        int p = tid - 64;
        const float* pn = nl + (size_t)b * NCLS * HW + rem + p;
        float l0 = pn[0], l1 = pn[HW], l2 = pn[2 * HW], l3 = pn[3 * HW];
        int amax = 0; float m = l0;
        if (l1 > m) { m = l1; amax = 1; }
        if (l2 > m) { m = l2; amax = 2; }
        if (l3 > m) { m = l3; amax = 3; }
        float sum = __expf(l0 - m) + __expf(l1 - m) + __expf(l2 - m) + __expf(l3 - m);
        g_segneg[px0 + p]  = amax;
        g_negprob[px0 + p] = 1.0f / sum;
    }
    __syncthreads();

    if (tid < 64) {
        float sx2 = 0.f, sp2 = 0.f, sxp = 0.f;
        #pragma unroll
        for (int g = 0; g < 8; g++) {
            sx2 += sRed[(0 * 8 + g) * 64 + tid];
            sp2 += sRed[(1 * 8 + g) * 64 + tid];
            sxp += sRed[(2 * 8 + g) * 64 + tid];
        }
        float invi = 1.0f / fmaxf(sqrtf(sx2), 1e-12f);
        float invp = 1.0f / fmaxf(sqrtf(sp2), 1e-12f);
        sInv[tid]  = invi;
        sInvP[tid] = invp;
        sNom[tid]  = exp2f(sxp * invi * invp * SCALE);
        atomicAdd(&sCnt[sCls[tid]], 1);
    }
    __syncthreads();
    if (tid == 0) {
        int acc = 0;
        #pragma unroll
        for (int c = 0; c < 4; c++) { sCnt[4 + c] = acc; acc += sCnt[c]; }
    }
    __syncthreads();
    if (tid < 64) {
        int pos2 = atomicAdd(&sCnt[4 + sCls[tid]], 1);
        sPerm[pos2] = tid;
        sSlot[tid]  = pos2;
    }
    __syncthreads();

    // store normalized x̂/p̂ at class-sorted rows (persists across barriers)
    {
        float invi = sInv[n], invp = sInvP[n];
        int slot = sSlot[n];
        float* dx = sX + slot * RS + cg * 16;
        float* dp = sP + slot * RS + cg * 16;
        #pragma unroll
        for (int j4 = 0; j4 < 4; j4++) {
            *(float4*)&dx[j4 * 4] = make_float4(xv[j4*4]*invi, xv[j4*4+1]*invi,
                                                xv[j4*4+2]*invi, xv[j4*4+3]*invi);
            *(float4*)&dp[j4 * 4] = make_float4(pv[j4*4]*invp, pv[j4*4+1]*invp,
                                                pv[j4*4+2]*invp, pv[j4*4+3]*invp);
        }
    }

    grid_barrier();   // ==== barrier 1: seg/prob visible ====

    // ======== Phase 2 (blocks 0..3): per-class top-50 + gather ========
    if (blk < NCLS) {
        // scratch aliased over the (not-yet-loaded) sG region
        int*   hist   = (int*)sG;
        int*   schunk = hist + NBIN;
        float* cv     = (float*)(schunk + 32);
        int*   ci     = (int*)(cv + MAXCAND);
        int*   ssel   = ci + MAXCAND;
        int*   sflag  = ssel + 64;       // [0]=cnt, [1]=binThr

        int s = blk;

        int  seg[16]; float pvv[16]; int bin[16];
        {
            const int4*   ps = (const int4*)g_segneg + tid * 4;
            const float4* pp = (const float4*)g_negprob + tid * 4;
            #pragma unroll
            for (int j4 = 0; j4 < 4; j4++) {
                int4 sv = ps[j4]; float4 fv = pp[j4];
                seg[j4*4+0]=sv.x; seg[j4*4+1]=sv.y; seg[j4*4+2]=sv.z; seg[j4*4+3]=sv.w;
                pvv[j4*4+0]=fv.x; pvv[j4*4+1]=fv.y; pvv[j4*4+2]=fv.z; pvv[j4*4+3]=fv.w;
            }
            #pragma unroll
            for (int j = 0; j < 16; j++) {
                int bb = (int)((pvv[j] - 0.25f) * (1024.0f / 0.75f));
                bin[j] = max(0, min(NBIN - 1, bb));
            }
        }
        for (int i = tid; i < NBIN; i += NTHR) hist[i] = 0;
        if (tid == 0) sflag[0] = 0;
        __syncthreads();

        #pragma unroll
        for (int j = 0; j < 16; j++)
            if (seg[j] != s) atomicAdd(&hist[bin[j]], 1);
        __syncthreads();

        if (tid < 32) {
            int sum = 0;
            #pragma unroll
            for (int j = 0; j < 32; j++) sum += hist[tid * 32 + j];
            schunk[tid] = sum;
        }
        __syncthreads();
        if (tid == 0) {
            int cum = 0, binThr = 0;
            for (int cb = 31; cb >= 0; cb--) {
                if (cum + schunk[cb] >= KSEL) {
                    for (int bb = cb * 32 + 31; bb >= cb * 32; bb--) {
                        cum += hist[bb];
                        if (cum >= KSEL) { binThr = bb; break; }
                    }
                    break;
                }
                cum += schunk[cb];
            }
            sflag[1] = binThr;
        }
        __syncthreads();
        int binThr = sflag[1];

        #pragma unroll
        for (int j = 0; j < 16; j++) {
            if (seg[j] != s && bin[j] >= binThr) {
                int p2 = atomicAdd(&sflag[0], 1);
                if (p2 < MAXCAND) { cv[p2] = pvv[j]; ci[p2] = tid * 16 + j; }
            }
        }
        __syncthreads();
        int M = min(sflag[0], MAXCAND);

        // exact rank (value desc, index asc tie-break == lax.top_k)
        for (int c = tid; c < M; c += NTHR) {
            float v = cv[c]; int id = ci[c];
            int r = 0;
            for (int m = 0; m < M; m++) {
                float vm = cv[m];
                if (vm > v || (vm == v && ci[m] < id)) r++;
            }
            if (r < KSEL) ssel[r] = id;
        }
        __syncthreads();

        // gather + normalize + pre-scale 50 negatives (16 warps)
        {
            int w = tid >> 5, lane = tid & 31;
            for (int k = w; k < KSEL; k += 16) {
                int nn = ssel[k];
                int bb = nn >> 12, rr = nn & 4095;
                const float* p = neg + (size_t)bb * CC * HW + rr;
                float v[4]; float ss = 0.f;
                #pragma unroll
                for (int j = 0; j < 4; j++) {
                    int c = lane + j * 32;
                    v[j] = p[(size_t)c * HW];
                    ss += v[j] * v[j];
                }
                #pragma unroll
                for (int off = 16; off; off >>= 1) ss += __shfl_xor_sync(0xffffffffu, ss, off);
                float inv = SCALE / fmaxf(sqrtf(ss), 1e-12f);
                #pragma unroll
                for (int j = 0; j < 4; j++) {
                    int c = lane + j * 32;
                    g_Gs[s][k][c] = v[j] * inv;
                }
            }
        }
    }

    grid_barrier();   // ==== barrier 2: g_Gs visible ====

    // ======== Phase 3: load G to smem, GEMM, loss ========
    {
        const float4* gsrc = (const float4*)g_Gs;     // 4*56*128/4 = 7168 float4
        #pragma unroll
        for (int it = 0; it < 14; it++) {
            int f4 = tid + it * NTHR;
            int cls = f4 / 1792;
            int r4  = f4 - cls * 1792;
            float4 v = gsrc[f4];
            *(float4*)&sG[cls * CS + r4 * 4] = v;
        }
    }
    __syncthreads();

    {
        int lane = tid & 31, w = tid >> 5;           // 16 warps
        int half = w & 1, kg = w >> 1;               // kg 0..7, 7 k's each
        int slot = half * 32 + lane;
        int cls  = sCls[sPerm[slot]];
        const float* gx = sX + slot * RS;
        const float* gp = sP + slot * RS;
        const float* gg = sG + cls * CS + (kg * 7) * CC;

        u64 aN[7], aA[7];
        #pragma unroll
        for (int kk = 0; kk < 7; kk++) { aN[kk] = 0ull; aA[kk] = 0ull; }

        #pragma unroll 4
        for (int c4 = 0; c4 < 32; c4++) {
            ulonglong2 x2 = *(const ulonglong2*)&gx[c4 * 4];
            ulonglong2 p2 = *(const ulonglong2*)&gp[c4 * 4];
            #pragma unroll
            for (int kk = 0; kk < 7; kk++) {
                ulonglong2 g2 = *(const ulonglong2*)&gg[kk * CC + c4 * 4];
                fma2(aN[kk], x2.x, g2.x); fma2(aN[kk], x2.y, g2.y);
                fma2(aA[kk], p2.x, g2.x); fma2(aA[kk], p2.y, g2.y);
            }
        }

        float eN = 0.f, eA = 0.f;
        #pragma unroll
        for (int kk = 0; kk < 7; kk++) {
            if (kg * 7 + kk < KSEL) {
                float2 tn = upk(aN[kk]);
                float2 ta = upk(aA[kk]);
                eN += exp2f(tn.x + tn.y);
                eA += exp2f(ta.x + ta.y);
            }
        }
        sEx[kg * 64 + slot]       = eN;
        sEx[(8 + kg) * 64 + slot] = eA;
    }
    __syncthreads();

    if (tid < 64) {
        float accN = 0.f, accA = 0.f;
        #pragma unroll
        for (int g = 0; g < 8; g++) {
            accN += sEx[g * 64 + tid];
            accA += sEx[(8 + g) * 64 + tid];
        }
        float nom = sNom[sPerm[tid]];
        float term = logf(nom / (accN + nom + 1e-8f))
                   + logf(nom / (accA + nom + 1e-8f));
        #pragma unroll
        for (int off = 16; off; off >>= 1)
            term += __shfl_xor_sync(0xffffffffu, term, off);
        if ((tid & 31) == 0) atomicAdd(&g_acc, term);
    }
    __syncthreads();

    if (tid == 0) {
        __threadfence();
        unsigned int ticket = atomicAdd(&g_tick, 1u);
        if (ticket == NBLK - 1) {
            float v = atomicAdd(&g_acc, 0.0f);
            out[0] = -v / (float)NPIX;
            g_tick = 0u;
        }
    }
}

// ---------------- launch ----------------
extern "C" void kernel_launch(void* const* d_in, const int* in_sizes, int n_in,
                              void* d_out, int out_size) {
    const float* inp = (const float*)d_in[0];   // input    [2,128,64,64]
    const float* pos = (const float*)d_in[1];   // positive
    const float* neg = (const float*)d_in[2];   // negative
    const float* il  = (const float*)d_in[3];   // input_logits    [2,4,64,64]
    const float* nl  = (const float*)d_in[4];   // negative_logits
    float* out = (float*)d_out;

    cudaFuncSetAttribute(k_all, cudaFuncAttributeMaxDynamicSharedMemorySize, SMEM_BYTES);
    k_all<<<NBLK, NTHR, SMEM_BYTES>>>(inp, pos, neg, il, nl, out);
}